// round 2
// baseline (speedup 1.0000x reference)
#include <cuda_runtime.h>
#include <cstdint>

#define NROWS   131072
#define DDIM    512
#define NCLS    100
#define LAMBDA  0.001f
#define SPLITK  16
#define KCHUNK  (NROWS / SPLITK)
#define MAT     (DDIM * DDIM)

__device__ float g_cls_sums[NCLS * DDIM];
__device__ float g_counts[NCLS];
__device__ float g_mean[DDIM];
__device__ float g_cmean[NCLS * DDIM];
__device__ float g_wc[NCLS];
__device__ float g_wcc[NCLS];
__device__ float g_cw[NCLS];
__device__ float g_P1[SPLITK * MAT];
__device__ float g_P2[SPLITK * MAT];
__device__ float g_G1[MAT];
__device__ float g_G2[MAT];
__device__ float g_M[MAT];
__device__ float g_XA[MAT];
__device__ float g_XB[MAT];
__device__ float g_T[MAT];
__device__ float g_invR;

__constant__ int c_bi[10] = {0,1,1,2,2,2,3,3,3,3};
__constant__ int c_bj[10] = {0,0,1,0,1,2,0,1,2,3};

// packed f32x2 helpers
__device__ __forceinline__ unsigned long long pk2(float a, float b) {
    unsigned long long r; asm("mov.b64 %0, {%1, %2};" : "=l"(r) : "f"(a), "f"(b)); return r;
}
__device__ __forceinline__ void upk2(unsigned long long v, float& a, float& b) {
    asm("mov.b64 {%0, %1}, %2;" : "=f"(a), "=f"(b) : "l"(v));
}
__device__ __forceinline__ unsigned long long mul2(unsigned long long a, unsigned long long b) {
    unsigned long long r; asm("mul.rn.f32x2 %0, %1, %2;" : "=l"(r) : "l"(a), "l"(b)); return r;
}
__device__ __forceinline__ unsigned long long add2(unsigned long long a, unsigned long long b) {
    unsigned long long r; asm("add.rn.f32x2 %0, %1, %2;" : "=l"(r) : "l"(a), "l"(b)); return r;
}
__device__ __forceinline__ unsigned long long fma2(unsigned long long a, unsigned long long b,
                                                   unsigned long long c) {
    unsigned long long r; asm("fma.rn.f32x2 %0, %1, %2, %3;" : "=l"(r) : "l"(a), "l"(b), "l"(c)); return r;
}

// kernel 1: per-class column sums + counts (ballot scan, no atomics)
__global__ void k_stats(const float4* __restrict__ X4, const int* __restrict__ y) {
    const int c = blockIdx.x, cg = blockIdx.y;
    const int tid = threadIdx.x, w = tid >> 5, lane = tid & 31;
    const int4* y4 = (const int4*)y;
    float4 acc = make_float4(0.f, 0.f, 0.f, 0.f);
    int cnt = 0;
    int idx = w * 4096 + lane;
    int4 cur = y4[idx];
    for (int s = 0; s < 128; ++s) {
        int4 nxt = make_int4(0, 0, 0, 0);
        if (s < 127) nxt = y4[idx + 32];
        const int rowbase = w * 16384 + s * 128;
#pragma unroll
        for (int q = 0; q < 4; ++q) {
            int yq = (q == 0) ? cur.x : (q == 1) ? cur.y : (q == 2) ? cur.z : cur.w;
            unsigned m = __ballot_sync(0xffffffffu, yq == c);
            cnt += __popc(m);
            while (m) {
                int b = __ffs(m) - 1; m &= m - 1;
                float4 v = X4[(size_t)(rowbase + b * 4 + q) * 128 + cg * 32 + lane];
                acc.x += v.x; acc.y += v.y; acc.z += v.z; acc.w += v.w;
            }
        }
        cur = nxt; idx += 32;
    }
    __shared__ float4 sa[8][32];
    __shared__ int sc[8];
    sa[w][lane] = acc;
    if (lane == 0) sc[w] = cnt;
    __syncthreads();
    if (tid < 32) {
        float4 t = sa[0][tid];
#pragma unroll
        for (int ww = 1; ww < 8; ++ww) {
            float4 v = sa[ww][tid];
            t.x += v.x; t.y += v.y; t.z += v.z; t.w += v.w;
        }
        float* dst = &g_cls_sums[c * DDIM + cg * 128 + tid * 4];
        dst[0] = t.x; dst[1] = t.y; dst[2] = t.z; dst[3] = t.w;
    }
    if (tid == 0 && cg == 0) {
        int tot = 0;
#pragma unroll
        for (int ww = 0; ww < 8; ++ww) tot += sc[ww];
        g_counts[c] = (float)tot;
    }
}

// kernel 2: means / weights
__global__ void k_small(float* __restrict__ o_mu) {
    const int t = threadIdx.x;
    if (t < DDIM) {
        float s = 0.f;
        for (int c = 0; c < NCLS; ++c) s += g_cls_sums[c * DDIM + t];
        float mean = s / (float)NROWS;
        g_mean[t] = mean;
        o_mu[t] = mean;
    }
    if (t < NCLS) {
        float cnt = g_counts[t];
        float wc = cnt / fmaxf(cnt - 1.0f, 1.0f) / (float)NROWS;
        g_wc[t] = wc;
        g_wcc[t] = wc * cnt;
        g_cw[t] = cnt / (float)NROWS;
    }
    for (int i = t; i < NCLS * DDIM; i += 512) {
        int c = i >> 9;
        g_cmean[i] = g_cls_sums[i] / fmaxf(g_counts[c], 1.0f);
    }
}

// kernel 3: fused dual gram, f32x2 pipe, 128x128 tile, split-K partials
__global__ __launch_bounds__(256, 1) void k_gram(const float4* __restrict__ X4,
                                                 const int* __restrict__ y) {
    const int t = blockIdx.x % 10, s = blockIdx.x / 10;
    const int bi = c_bi[t], bj = c_bj[t];
    const int k0 = s * KCHUNK;

    __shared__ float As[16][128];
    __shared__ float Bs[16][128];
    __shared__ float ws[16];

    const int tid = threadIdx.x;
    const int tx = tid & 15, ty = tid >> 4;

    unsigned long long c1[8][4], c2[8][4];
#pragma unroll
    for (int r = 0; r < 8; ++r)
#pragma unroll
        for (int p = 0; p < 4; ++p) { c1[r][p] = 0ull; c2[r][p] = 0ull; }

    float4* As4 = (float4*)As;
    float4* Bs4 = (float4*)Bs;

    for (int kb = 0; kb < KCHUNK; kb += 16) {
        __syncthreads();
#pragma unroll
        for (int q = 0; q < 2; ++q) {
            int idx = tid + q * 256;
            int kk = idx >> 5, c4 = idx & 31;
            As4[idx] = X4[(size_t)(k0 + kb + kk) * 128 + bi * 32 + c4];
            Bs4[idx] = X4[(size_t)(k0 + kb + kk) * 128 + bj * 32 + c4];
        }
        if (tid < 16) ws[tid] = g_wc[y[k0 + kb + tid]];
        __syncthreads();

#pragma unroll
        for (int kk = 0; kk < 16; ++kk) {
            float4 a0 = *(const float4*)&As[kk][ty * 8];
            float4 a1 = *(const float4*)&As[kk][ty * 8 + 4];
            float4 b0 = *(const float4*)&Bs[kk][tx * 8];
            float4 b1 = *(const float4*)&Bs[kk][tx * 8 + 4];
            unsigned long long b2[4] = { pk2(b0.x, b0.y), pk2(b0.z, b0.w),
                                         pk2(b1.x, b1.y), pk2(b1.z, b1.w) };
            float wv = ws[kk];
            unsigned long long w2 = pk2(wv, wv);
            float av[8] = { a0.x, a0.y, a0.z, a0.w, a1.x, a1.y, a1.z, a1.w };
#pragma unroll
            for (int r = 0; r < 8; ++r) {
                unsigned long long a2 = pk2(av[r], av[r]);
#pragma unroll
                for (int p = 0; p < 4; ++p) {
                    unsigned long long pr = mul2(a2, b2[p]);
                    c1[r][p] = add2(c1[r][p], pr);
                    c2[r][p] = fma2(pr, w2, c2[r][p]);
                }
            }
        }
    }

    float* P1 = g_P1 + (size_t)s * MAT;
    float* P2 = g_P2 + (size_t)s * MAT;
#pragma unroll
    for (int r = 0; r < 8; ++r) {
        int row = bi * 128 + ty * 8 + r;
#pragma unroll
        for (int p = 0; p < 4; ++p) {
            int col = bj * 128 + tx * 8 + p * 2;
            float lo, hi;
            upk2(c1[r][p], lo, hi);
            *(float2*)&P1[(size_t)row * DDIM + col] = make_float2(lo, hi);
            upk2(c2[r][p], lo, hi);
            *(float2*)&P2[(size_t)row * DDIM + col] = make_float2(lo, hi);
        }
    }
}

// kernel 4: split-K reduce
__global__ void k_reduce() {
    int e = blockIdx.x * blockDim.x + threadIdx.x;
    float s1 = 0.f, s2 = 0.f;
#pragma unroll
    for (int s = 0; s < SPLITK; ++s) {
        s1 += g_P1[s * MAT + e];
        s2 += g_P2[s * MAT + e];
    }
    g_G1[e] = s1;
    g_G2[e] = s2;
}

// kernel 5: finalize St/Sw/Sb, build M = Sw + lambda I
__global__ void k_finalize(float* __restrict__ out) {
    float* o_sw = out + DDIM + MAT;
    float* o_sb = out + DDIM + 2 * MAT;
    float* o_st = out + DDIM + 3 * MAT;

    __shared__ float cmi[NCLS][16], cmj[NCLS][16];
    __shared__ float swcc[NCLS], scw[NCLS];

    const int tx = threadIdx.x, ty = threadIdx.y;
    const int tid = ty * 16 + tx;
    const int i0 = blockIdx.y * 16, j0 = blockIdx.x * 16;

    for (int idx = tid; idx < NCLS * 16; idx += 256) {
        int c = idx / 16, r = idx % 16;
        cmi[c][r] = g_cmean[c * DDIM + i0 + r];
        cmj[c][r] = g_cmean[c * DDIM + j0 + r];
    }
    if (tid < NCLS) { swcc[tid] = g_wcc[tid]; scw[tid] = g_cw[tid]; }
    __syncthreads();

    const int i = i0 + ty, j = j0 + tx;
    const float mi = g_mean[i], mj = g_mean[j];
    float swc = 0.f, sbv = 0.f;
#pragma unroll 4
    for (int c = 0; c < NCLS; ++c) {
        float a = cmi[c][ty], b = cmj[c][tx];
        swc += swcc[c] * a * b;
        sbv += scw[c] * (a - mi) * (b - mj);
    }

    int gidx = ((i >> 7) >= (j >> 7)) ? (i * DDIM + j) : (j * DDIM + i);
    float g1 = g_G1[gidx], g2 = g_G2[gidx];

    float st = (g1 - (float)NROWS * mi * mj) * (1.0f / ((float)NROWS - 1.0f));
    float sw = g2 - swc;

    o_sw[i * DDIM + j] = sw;
    o_sb[i * DDIM + j] = sbv;
    o_st[i * DDIM + j] = st;
    g_M[i * DDIM + j] = sw + ((i == j) ? LAMBDA : 0.0f);
}

// kernel 6: Gershgorin bound 1/R  (M symmetric -> column abs sums)
__global__ void k_rowmax() {
    const int t = threadIdx.x;
    float s = 0.f;
    for (int i = 0; i < DDIM; ++i) s += fabsf(g_M[i * DDIM + t]);
    __shared__ float sh[512];
    sh[t] = s;
    __syncthreads();
    for (int o = 256; o > 0; o >>= 1) {
        if (t < o) sh[t] = fmaxf(sh[t], sh[t + o]);
        __syncthreads();
    }
    if (t == 0) g_invR = 1.0f / sh[0];
}

// kernel 7: X0 = I / R
__global__ void k_ns_init() {
    int idx = blockIdx.x * 512 + threadIdx.x;
    g_XA[idx] = ((idx >> 9) == (idx & 511)) ? g_invR : 0.0f;
}

__device__ __forceinline__ float* selptr(int s, float* out) {
    switch (s) {
        case 0: return g_M;
        case 1: return g_XA;
        case 2: return g_XB;
        case 3: return g_T;
        default: return out + DDIM + 2 * MAT;  // Sb
    }
}

// kernel 8: 512^3 GEMM; mode 1: C = 2A - A@B
__global__ void k_gemm512(int aSel, int bSel, int cSel, int mode, float* __restrict__ out) {
    const float* A = selptr(aSel, out);
    const float* B = selptr(bSel, out);
    float* C = selptr(cSel, out);

    __shared__ float As[32][33];
    __shared__ float Bs[32][33];

    const int tx = threadIdx.x, ty = threadIdx.y;
    const int tid = ty * 16 + tx;
    const int i0 = blockIdx.y * 32, j0 = blockIdx.x * 32;

    float a00 = 0.f, a01 = 0.f, a10 = 0.f, a11 = 0.f;

    for (int k0 = 0; k0 < DDIM; k0 += 32) {
        __syncthreads();
#pragma unroll
        for (int q = 0; q < 4; ++q) {
            int idx = tid + q * 256;
            int r = idx >> 5, cc = idx & 31;
            As[r][cc] = A[(size_t)(i0 + r) * DDIM + k0 + cc];
            Bs[r][cc] = B[(size_t)(k0 + r) * DDIM + j0 + cc];
        }
        __syncthreads();
#pragma unroll
        for (int k = 0; k < 32; ++k) {
            float x0 = As[ty * 2][k], x1 = As[ty * 2 + 1][k];
            float b0 = Bs[k][tx * 2], b1 = Bs[k][tx * 2 + 1];
            a00 += x0 * b0; a01 += x0 * b1;
            a10 += x1 * b0; a11 += x1 * b1;
        }
    }

    const int i = i0 + ty * 2, j = j0 + tx * 2;
    if (mode == 1) {
        C[(size_t)i * DDIM + j]           = 2.0f * A[(size_t)i * DDIM + j]           - a00;
        C[(size_t)i * DDIM + j + 1]       = 2.0f * A[(size_t)i * DDIM + j + 1]       - a01;
        C[(size_t)(i + 1) * DDIM + j]     = 2.0f * A[(size_t)(i + 1) * DDIM + j]     - a10;
        C[(size_t)(i + 1) * DDIM + j + 1] = 2.0f * A[(size_t)(i + 1) * DDIM + j + 1] - a11;
    } else {
        C[(size_t)i * DDIM + j]           = a00;
        C[(size_t)i * DDIM + j + 1]       = a01;
        C[(size_t)(i + 1) * DDIM + j]     = a10;
        C[(size_t)(i + 1) * DDIM + j + 1] = a11;
    }
}

// kernel 9: temp = (T + T^T)/2
__global__ void k_symmetrize(float* __restrict__ out) {
    int idx = blockIdx.x * 512 + threadIdx.x;
    int i = idx >> 9, j = idx & 511;
    out[DDIM + idx] = 0.5f * (g_T[i * DDIM + j] + g_T[j * DDIM + i]);
}

extern "C" void kernel_launch(void* const* d_in, const int* in_sizes, int n_in,
                              void* d_out, int out_size) {
    const float4* X4 = (const float4*)d_in[0];
    const int* y = (const int*)d_in[1];
    float* out = (float*)d_out;

    k_stats<<<dim3(NCLS, 4), 256>>>(X4, y);
    k_small<<<1, 512>>>(out);
    k_gram<<<10 * SPLITK, 256>>>(X4, y);
    k_reduce<<<MAT / 512, 512>>>();
    k_finalize<<<dim3(32, 32), dim3(16, 16)>>>(out);
    k_rowmax<<<1, 512>>>();
    k_ns_init<<<MAT / 512, 512>>>();

    dim3 gg(16, 16), gb(16, 16);
    int cur = 1, nxt = 2;
    for (int it = 0; it < 8; ++it) {
        k_gemm512<<<gg, gb>>>(0, cur, 3, 0, out);   // T = M @ X
        k_gemm512<<<gg, gb>>>(cur, 3, nxt, 1, out); // Xn = 2X - X@T
        int tmp = cur; cur = nxt; nxt = tmp;
    }
    k_gemm512<<<gg, gb>>>(cur, 4, 3, 0, out);       // T = inv(M) @ Sb
    k_symmetrize<<<MAT / 512, 512>>>(out);
}

// round 4
// speedup vs baseline: 3.2631x; 3.2631x over previous
#include <cuda_runtime.h>
#include <cuda_bf16.h>
#include <cstdint>

#define NROWS   131072
#define DDIM    512
#define NCLS    100
#define LAMBDA  0.001f
#define SPLITS  14
#define NTILES  10
#define MAT     (DDIM * DDIM)
#define KBLK    64
#define NKB     (NROWS / KBLK)   // 2048

// ---------------- device scratch ----------------
__device__ float g_cls_sums[NCLS * DDIM];
__device__ float g_counts[NCLS];
__device__ float g_mean[DDIM];
__device__ float g_cmean[NCLS * DDIM];
__device__ float g_wc[NCLS];
__device__ float g_wcc[NCLS];
__device__ float g_cw[NCLS];
__device__ float g_wrow[NROWS];
__device__ __nv_bfloat16 g_H [DDIM * NROWS];   // K-major: [d][n]
__device__ __nv_bfloat16 g_L [DDIM * NROWS];
__device__ __nv_bfloat16 g_WH[DDIM * NROWS];
__device__ __nv_bfloat16 g_WL[DDIM * NROWS];
__device__ float g_P1[SPLITS * MAT];
__device__ float g_P2[SPLITS * MAT];
__device__ float g_G1[MAT];
__device__ float g_G2[MAT];
__device__ float g_M[MAT];
__device__ float g_XA[MAT];
__device__ float g_XB[MAT];
__device__ float g_T[MAT];
__device__ float g_invR;

__constant__ int c_bi[NTILES] = {0,1,1,2,2,2,3,3,3,3};
__constant__ int c_bj[NTILES] = {0,0,1,0,1,2,0,1,2,3};

// ---------------- PTX helpers (all plain sm_80/90 features, no 'a' required) ----------------
__device__ __forceinline__ uint32_t smem_u32(const void* p) {
    uint32_t a;
    asm("{ .reg .u64 t; cvta.to.shared.u64 t, %1; cvt.u32.u64 %0, t; }" : "=r"(a) : "l"(p));
    return a;
}
__device__ __forceinline__ void cp_async16(uint32_t s, const void* g) {
    asm volatile("cp.async.cg.shared.global [%0], [%1], 16;" :: "r"(s), "l"(g) : "memory");
}
#define CP_COMMIT()  asm volatile("cp.async.commit_group;" ::: "memory")
#define CP_WAIT1()   asm volatile("cp.async.wait_group 1;" ::: "memory")
#define CP_WAIT0()   asm volatile("cp.async.wait_group 0;" ::: "memory")

__device__ __forceinline__ void ldsm_x4(uint32_t& r0, uint32_t& r1, uint32_t& r2, uint32_t& r3,
                                        uint32_t a) {
    asm volatile("ldmatrix.sync.aligned.m8n8.x4.shared.b16 {%0,%1,%2,%3}, [%4];"
                 : "=r"(r0), "=r"(r1), "=r"(r2), "=r"(r3) : "r"(a));
}
__device__ __forceinline__ void mma16816(float* c, const uint32_t* a, uint32_t b0, uint32_t b1) {
    asm volatile("mma.sync.aligned.m16n8k16.row.col.f32.bf16.bf16.f32 "
                 "{%0,%1,%2,%3}, {%4,%5,%6,%7}, {%8,%9}, {%0,%1,%2,%3};"
                 : "+f"(c[0]), "+f"(c[1]), "+f"(c[2]), "+f"(c[3])
                 : "r"(a[0]), "r"(a[1]), "r"(a[2]), "r"(a[3]), "r"(b0), "r"(b1));
}
__device__ __forceinline__ uint32_t sw128(uint32_t b) { return b ^ ((b >> 3) & 0x70); }

// ---------------- kernel 1: per-class column sums + counts ----------------
__global__ void k_stats(const float4* __restrict__ X4, const int* __restrict__ y) {
    const int c = blockIdx.x, cg = blockIdx.y;
    const int tid = threadIdx.x, w = tid >> 5, lane = tid & 31;
    const int4* y4 = (const int4*)y;
    float4 acc = make_float4(0.f, 0.f, 0.f, 0.f);
    int cnt = 0;
    int idx = w * 4096 + lane;
    int4 cur = y4[idx];
    for (int s = 0; s < 128; ++s) {
        int4 nxt = make_int4(0, 0, 0, 0);
        if (s < 127) nxt = y4[idx + 32];
        const int rowbase = w * 16384 + s * 128;
#pragma unroll
        for (int q = 0; q < 4; ++q) {
            int yq = (q == 0) ? cur.x : (q == 1) ? cur.y : (q == 2) ? cur.z : cur.w;
            unsigned m = __ballot_sync(0xffffffffu, yq == c);
            cnt += __popc(m);
            while (m) {
                int b = __ffs(m) - 1; m &= m - 1;
                float4 v = X4[(size_t)(rowbase + b * 4 + q) * 128 + cg * 32 + lane];
                acc.x += v.x; acc.y += v.y; acc.z += v.z; acc.w += v.w;
            }
        }
        cur = nxt; idx += 32;
    }
    __shared__ float4 sa[8][32];
    __shared__ int sc[8];
    sa[w][lane] = acc;
    if (lane == 0) sc[w] = cnt;
    __syncthreads();
    if (tid < 32) {
        float4 t = sa[0][tid];
#pragma unroll
        for (int ww = 1; ww < 8; ++ww) {
            float4 v = sa[ww][tid];
            t.x += v.x; t.y += v.y; t.z += v.z; t.w += v.w;
        }
        float* dst = &g_cls_sums[c * DDIM + cg * 128 + tid * 4];
        dst[0] = t.x; dst[1] = t.y; dst[2] = t.z; dst[3] = t.w;
    }
    if (tid == 0 && cg == 0) {
        int tot = 0;
#pragma unroll
        for (int ww = 0; ww < 8; ++ww) tot += sc[ww];
        g_counts[c] = (float)tot;
    }
}

// ---------------- kernel 2: means / weights ----------------
__global__ void k_small(float* __restrict__ o_mu) {
    const int t = threadIdx.x;
    if (t < DDIM) {
        float s = 0.f;
        for (int c = 0; c < NCLS; ++c) s += g_cls_sums[c * DDIM + t];
        float mean = s / (float)NROWS;
        g_mean[t] = mean;
        o_mu[t] = mean;
    }
    if (t < NCLS) {
        float cnt = g_counts[t];
        float wc = cnt / fmaxf(cnt - 1.0f, 1.0f) / (float)NROWS;
        g_wc[t] = wc;
        g_wcc[t] = wc * cnt;
        g_cw[t] = cnt / (float)NROWS;
    }
    for (int i = t; i < NCLS * DDIM; i += 512) {
        int c = i >> 9;
        g_cmean[i] = g_cls_sums[i] / fmaxf(g_counts[c], 1.0f);
    }
}

// ---------------- kernel 2b: per-row weight ----------------
__global__ void k_wrow(const int* __restrict__ y) {
    int n = blockIdx.x * 512 + threadIdx.x;
    g_wrow[n] = g_wc[y[n]];
}

// ---------------- kernel 3: transpose + bf16 hi/lo split ----------------
__global__ void k_convert(const float* __restrict__ X) {
    __shared__ float t[64][65];
    __shared__ float wv[64];
    const int n0 = blockIdx.x * 64, d0 = blockIdx.y * 64;
    const int tid = threadIdx.x;
    for (int i = tid; i < 4096; i += 256) {
        int r = i >> 6, c = i & 63;
        t[r][c] = X[(size_t)(n0 + r) * DDIM + d0 + c];
    }
    if (tid < 64) wv[tid] = g_wrow[n0 + tid];
    __syncthreads();
    for (int i = tid; i < 4096; i += 256) {
        int d = i >> 6, nn = i & 63;
        float x = t[nn][d];
        __nv_bfloat16 h = __float2bfloat16(x);
        __nv_bfloat16 l = __float2bfloat16(x - __bfloat162float(h));
        float xw = wv[nn] * x;
        __nv_bfloat16 wh = __float2bfloat16(xw);
        __nv_bfloat16 wl = __float2bfloat16(xw - __bfloat162float(wh));
        size_t o = (size_t)(d0 + d) * NROWS + n0 + nn;
        g_H[o] = h; g_L[o] = l; g_WH[o] = wh; g_WL[o] = wl;
    }
}

// ---------------- kernel 4: HMMA dual gram ----------------
// 256 threads = 8 warps. Warps 0-3: G1 (Hi,Li)x(Hj,Lj). Warps 4-7: G2 (Hi,Li)x(WHj,WLj).
// Each warp: 64x64 quadrant, 3 chains, fp32 reg accumulators.
// smem: 2 stages x 6 tiles x (128 rows x 64 bf16 = 16KB, SW128).
#define STAGE_BYTES (6 * 16384)

__global__ __launch_bounds__(256, 1)
void k_gram_mma() {
    extern __shared__ char dsm[];
    const uint32_t sbase = (smem_u32(dsm) + 1023u) & ~1023u;

    const int tile = blockIdx.x % NTILES;
    const int sp   = blockIdx.x / NTILES;
    const int bi = c_bi[tile] * 128, bj = c_bj[tile] * 128;
    const int kb0 = (NKB * sp) / SPLITS;
    const int kb1 = (NKB * (sp + 1)) / SPLITS;
    const int n = kb1 - kb0;

    const int tid = threadIdx.x;
    const int w = tid >> 5, lane = tid & 31;
    const int grp = w >> 2;              // 0 = G1, 1 = G2
    const int wm = w & 1, wn = (w >> 1) & 1;

    // stage loader: 6 tiles of [128][64] bf16, SW128, cp.async
    auto load_stage = [&](int stg, int kb) {
        uint32_t stb = sbase + stg * STAGE_BYTES;
#pragma unroll
        for (int i = 0; i < 24; ++i) {
            const int t6 = i >> 2;
            int rem = (i & 3) * 256 + tid;
            int r = rem >> 3, c = rem & 7;
            uint32_t sw = sw128((uint32_t)(r * 128 + c * 16));
            const __nv_bfloat16* base;
            int row;
            if      (t6 == 0) { base = g_H;  row = bi; }
            else if (t6 == 1) { base = g_L;  row = bi; }
            else if (t6 == 2) { base = g_H;  row = bj; }
            else if (t6 == 3) { base = g_L;  row = bj; }
            else if (t6 == 4) { base = g_WH; row = bj; }
            else              { base = g_WL; row = bj; }
            const void* g = base + (size_t)(row + r) * NROWS + (size_t)kb * KBLK + c * 8;
            cp_async16(stb + t6 * 16384 + sw, g);
        }
        CP_COMMIT();
    };

    float acc[4][8][4];
#pragma unroll
    for (int m = 0; m < 4; ++m)
#pragma unroll
        for (int nn = 0; nn < 8; ++nn)
#pragma unroll
            for (int q = 0; q < 4; ++q) acc[m][nn][q] = 0.f;

    // per-lane intra-tile byte offsets (pre-swizzle)
    // A (m16k16 x4): row = warp_m*64 + mtile*16 + (lane&15); kbyte = (lane>>4)*16
    const uint32_t a_off = (uint32_t)((wm * 64 + (lane & 15)) * 128 + (lane >> 4) * 16);
    // B pair (two n-tiles per x4): row = wn*64 + nt2*16 + (lane&15); kbyte = (lane>>4)*16
    const uint32_t b_off = (uint32_t)((wn * 64 + (lane & 15)) * 128 + (lane >> 4) * 16);

    const uint32_t tA0 = 0, tA1 = 16384;                       // Hi, Li
    const uint32_t tB0 = grp ? 4 * 16384 : 2 * 16384;          // Hj | WHj
    const uint32_t tB1 = tB0 + 16384;                          // Lj | WLj

    load_stage(0, kb0);

    for (int i = 0; i < n; ++i) {
        const int b = i & 1;
        if (i + 1 < n) { load_stage(b ^ 1, kb0 + i + 1); CP_WAIT1(); }
        else           { CP_WAIT0(); }
        __syncthreads();

        const uint32_t st = sbase + b * STAGE_BYTES;
#pragma unroll
        for (int ks = 0; ks < 4; ++ks) {
            const uint32_t kb_byte = ks * 32;
            uint32_t aH[4][4], aL[4][4];
#pragma unroll
            for (int m = 0; m < 4; ++m) {
                uint32_t off = a_off + (uint32_t)(m * 16 * 128) + kb_byte;
                ldsm_x4(aH[m][0], aH[m][1], aH[m][2], aH[m][3], st + tA0 + sw128(off));
                ldsm_x4(aL[m][0], aL[m][1], aL[m][2], aL[m][3], st + tA1 + sw128(off));
            }
#pragma unroll
            for (int nt2 = 0; nt2 < 4; ++nt2) {
                uint32_t off = b_off + (uint32_t)(nt2 * 16 * 128) + kb_byte;
                uint32_t bh0, bh1, bh2, bh3, bl0, bl1, bl2, bl3;
                ldsm_x4(bh0, bh1, bh2, bh3, st + tB0 + sw128(off));
                ldsm_x4(bl0, bl1, bl2, bl3, st + tB1 + sw128(off));
                // regs: (r0,r2) = b-frag for ntile=2*nt2 ; (r1,r3) = ntile=2*nt2+1
#pragma unroll
                for (int m = 0; m < 4; ++m) {
                    float* c0 = acc[m][nt2 * 2];
                    float* c1 = acc[m][nt2 * 2 + 1];
                    mma16816(c0, aH[m], bh0, bh2);
                    mma16816(c0, aH[m], bl0, bl2);
                    mma16816(c0, aL[m], bh0, bh2);
                    mma16816(c1, aH[m], bh1, bh3);
                    mma16816(c1, aH[m], bl1, bl3);
                    mma16816(c1, aL[m], bh1, bh3);
                }
            }
        }
        __syncthreads();
    }

    // write deterministic split-K partials
    float* P = (grp == 0 ? g_P1 : g_P2) + (size_t)sp * MAT;
#pragma unroll
    for (int m = 0; m < 4; ++m) {
#pragma unroll
        for (int nn = 0; nn < 8; ++nn) {
            int row = bi + wm * 64 + m * 16 + (lane >> 2);
            int col = bj + wn * 64 + nn * 8 + (lane & 3) * 2;
            *(float2*)&P[(size_t)row * DDIM + col]       = make_float2(acc[m][nn][0], acc[m][nn][1]);
            *(float2*)&P[(size_t)(row + 8) * DDIM + col] = make_float2(acc[m][nn][2], acc[m][nn][3]);
        }
    }
}

// ---------------- kernel 5: split-K reduce ----------------
__global__ void k_reduce() {
    int e = blockIdx.x * blockDim.x + threadIdx.x;
    float s1 = 0.f, s2 = 0.f;
#pragma unroll
    for (int s = 0; s < SPLITS; ++s) {
        s1 += g_P1[s * MAT + e];
        s2 += g_P2[s * MAT + e];
    }
    g_G1[e] = s1;
    g_G2[e] = s2;
}

// ---------------- kernel 6: finalize St/Sw/Sb, build M ----------------
__global__ void k_finalize(float* __restrict__ out) {
    float* o_sw = out + DDIM + MAT;
    float* o_sb = out + DDIM + 2 * MAT;
    float* o_st = out + DDIM + 3 * MAT;

    __shared__ float cmi[NCLS][16], cmj[NCLS][16];
    __shared__ float swcc[NCLS], scw[NCLS];

    const int tx = threadIdx.x, ty = threadIdx.y;
    const int tid = ty * 16 + tx;
    const int i0 = blockIdx.y * 16, j0 = blockIdx.x * 16;

    for (int idx = tid; idx < NCLS * 16; idx += 256) {
        int c = idx / 16, r = idx % 16;
        cmi[c][r] = g_cmean[c * DDIM + i0 + r];
        cmj[c][r] = g_cmean[c * DDIM + j0 + r];
    }
    if (tid < NCLS) { swcc[tid] = g_wcc[tid]; scw[tid] = g_cw[tid]; }
    __syncthreads();

    const int i = i0 + ty, j = j0 + tx;
    const float mi = g_mean[i], mj = g_mean[j];
    float swc = 0.f, sbv = 0.f;
#pragma unroll 4
    for (int c = 0; c < NCLS; ++c) {
        float a = cmi[c][ty], b = cmj[c][tx];
        swc += swcc[c] * a * b;
        sbv += scw[c] * (a - mi) * (b - mj);
    }

    int gidx = ((i >> 7) >= (j >> 7)) ? (i * DDIM + j) : (j * DDIM + i);
    float g1 = g_G1[gidx], g2 = g_G2[gidx];

    float st = (g1 - (float)NROWS * mi * mj) * (1.0f / ((float)NROWS - 1.0f));
    float sw = g2 - swc;

    o_sw[i * DDIM + j] = sw;
    o_sb[i * DDIM + j] = sbv;
    o_st[i * DDIM + j] = st;
    g_M[i * DDIM + j] = sw + ((i == j) ? LAMBDA : 0.0f);
}

// ---------------- kernel 7: Gershgorin bound ----------------
__global__ void k_rowmax() {
    const int t = threadIdx.x;
    float s = 0.f;
    for (int i = 0; i < DDIM; ++i) s += fabsf(g_M[i * DDIM + t]);
    __shared__ float sh[512];
    sh[t] = s;
    __syncthreads();
    for (int o = 256; o > 0; o >>= 1) {
        if (t < o) sh[t] = fmaxf(sh[t], sh[t + o]);
        __syncthreads();
    }
    if (t == 0) g_invR = 1.0f / sh[0];
}

// ---------------- kernel 8: X0 = I / R ----------------
__global__ void k_ns_init() {
    int idx = blockIdx.x * 512 + threadIdx.x;
    g_XA[idx] = ((idx >> 9) == (idx & 511)) ? g_invR : 0.0f;
}

__device__ __forceinline__ float* selptr(int s, float* out) {
    switch (s) {
        case 0: return g_M;
        case 1: return g_XA;
        case 2: return g_XB;
        case 3: return g_T;
        default: return out + DDIM + 2 * MAT;  // Sb
    }
}

// ---------------- kernel 9: 512^3 GEMM; mode 1: C = 2A - A@B ----------------
__global__ void k_gemm512(int aSel, int bSel, int cSel, int mode, float* __restrict__ out) {
    const float* A = selptr(aSel, out);
    const float* B = selptr(bSel, out);
    float* C = selptr(cSel, out);

    __shared__ float As[32][33];
    __shared__ float Bs[32][33];

    const int tx = threadIdx.x, ty = threadIdx.y;
    const int tid = ty * 16 + tx;
    const int i0 = blockIdx.y * 32, j0 = blockIdx.x * 32;

    float a00 = 0.f, a01 = 0.f, a10 = 0.f, a11 = 0.f;

    for (int k0 = 0; k0 < DDIM; k0 += 32) {
        __syncthreads();
#pragma unroll
        for (int q = 0; q < 4; ++q) {
            int idx = tid + q * 256;
            int r = idx >> 5, cc = idx & 31;
            As[r][cc] = A[(size_t)(i0 + r) * DDIM + k0 + cc];
            Bs[r][cc] = B[(size_t)(k0 + r) * DDIM + j0 + cc];
        }
        __syncthreads();
#pragma unroll
        for (int k = 0; k < 32; ++k) {
            float x0 = As[ty * 2][k], x1 = As[ty * 2 + 1][k];
            float b0 = Bs[k][tx * 2], b1 = Bs[k][tx * 2 + 1];
            a00 += x0 * b0; a01 += x0 * b1;
            a10 += x1 * b0; a11 += x1 * b1;
        }
    }

    const int i = i0 + ty * 2, j = j0 + tx * 2;
    if (mode == 1) {
        C[(size_t)i * DDIM + j]           = 2.0f * A[(size_t)i * DDIM + j]           - a00;
        C[(size_t)i * DDIM + j + 1]       = 2.0f * A[(size_t)i * DDIM + j + 1]       - a01;
        C[(size_t)(i + 1) * DDIM + j]     = 2.0f * A[(size_t)(i + 1) * DDIM + j]     - a10;
        C[(size_t)(i + 1) * DDIM + j + 1] = 2.0f * A[(size_t)(i + 1) * DDIM + j + 1] - a11;
    } else {
        C[(size_t)i * DDIM + j]           = a00;
        C[(size_t)i * DDIM + j + 1]       = a01;
        C[(size_t)(i + 1) * DDIM + j]     = a10;
        C[(size_t)(i + 1) * DDIM + j + 1] = a11;
    }
}

// ---------------- kernel 10: temp = (T + T^T)/2 ----------------
__global__ void k_symmetrize(float* __restrict__ out) {
    int idx = blockIdx.x * 512 + threadIdx.x;
    int i = idx >> 9, j = idx & 511;
    out[DDIM + idx] = 0.5f * (g_T[i * DDIM + j] + g_T[j * DDIM + i]);
}

// ---------------- launcher ----------------
extern "C" void kernel_launch(void* const* d_in, const int* in_sizes, int n_in,
                              void* d_out, int out_size) {
    const float* X = (const float*)d_in[0];
    const int* y = (const int*)d_in[1];
    float* out = (float*)d_out;

    const int gram_smem = 2 * STAGE_BYTES + 1024;
    cudaFuncSetAttribute(k_gram_mma, cudaFuncAttributeMaxDynamicSharedMemorySize, gram_smem);

    k_stats<<<dim3(NCLS, 4), 256>>>((const float4*)X, y);
    k_small<<<1, 512>>>(out);
    k_wrow<<<NROWS / 512, 512>>>(y);
    k_convert<<<dim3(NROWS / 64, DDIM / 64), 256>>>(X);
    k_gram_mma<<<NTILES * SPLITS, 256, gram_smem>>>();
    k_reduce<<<MAT / 512, 512>>>();
    k_finalize<<<dim3(32, 32), dim3(16, 16)>>>(out);
    k_rowmax<<<1, 512>>>();
    k_ns_init<<<MAT / 512, 512>>>();

    dim3 gg(16, 16), gb(16, 16);
    int cur = 1, nxt = 2;
    for (int it = 0; it < 8; ++it) {
        k_gemm512<<<gg, gb>>>(0, cur, 3, 0, out);   // T = M @ X
        k_gemm512<<<gg, gb>>>(cur, 3, nxt, 1, out); // Xn = 2X - X@T
        int tmp = cur; cur = nxt; nxt = tmp;
    }
    k_gemm512<<<gg, gb>>>(cur, 4, 3, 0, out);       // T = inv(M) @ Sb
    k_symmetrize<<<MAT / 512, 512>>>(out);
}

// round 5
// speedup vs baseline: 4.3729x; 1.3401x over previous
#include <cuda_runtime.h>
#include <cuda_bf16.h>
#include <cstdint>

#define NROWS   131072
#define DDIM    512
#define NCLS    100
#define LAMBDA  0.001f
#define SPLITS  15
#define NTILES  10
#define MAT     (DDIM * DDIM)
#define KBLK    64
#define NKB     (NROWS / KBLK)   // 2048

// ---------------- device scratch ----------------
__device__ float g_cls_sums[NCLS * DDIM];
__device__ float g_counts[NCLS];
__device__ float g_mean[DDIM];
__device__ float g_cmean[NCLS * DDIM];
__device__ float g_wc[NCLS];
__device__ float g_wcc[NCLS];
__device__ float g_cw[NCLS];
__device__ float g_wrow[NROWS];
__device__ __nv_bfloat16 g_H [DDIM * NROWS];   // K-major: [d][n]
__device__ __nv_bfloat16 g_L [DDIM * NROWS];
__device__ __nv_bfloat16 g_WH[DDIM * NROWS];
__device__ float g_P1[SPLITS * MAT];
__device__ float g_P2[SPLITS * MAT];
__device__ float g_M[MAT];
__device__ float g_XA[MAT];
__device__ float g_XB[MAT];
__device__ float g_T[MAT];
__device__ float g_invR;

__constant__ int c_bi[NTILES] = {0,1,1,2,2,2,3,3,3,3};
__constant__ int c_bj[NTILES] = {0,0,1,0,1,2,0,1,2,3};

// ---------------- PTX helpers (plain sm_80-class features only) ----------------
__device__ __forceinline__ uint32_t smem_u32(const void* p) {
    uint32_t a;
    asm("{ .reg .u64 t; cvta.to.shared.u64 t, %1; cvt.u32.u64 %0, t; }" : "=r"(a) : "l"(p));
    return a;
}
__device__ __forceinline__ void cp_async16(uint32_t s, const void* g) {
    asm volatile("cp.async.cg.shared.global [%0], [%1], 16;" :: "r"(s), "l"(g) : "memory");
}
#define CP_COMMIT()  asm volatile("cp.async.commit_group;" ::: "memory")
#define CP_WAIT1()   asm volatile("cp.async.wait_group 1;" ::: "memory")
#define CP_WAIT0()   asm volatile("cp.async.wait_group 0;" ::: "memory")

__device__ __forceinline__ void ldsm_x4(uint32_t& r0, uint32_t& r1, uint32_t& r2, uint32_t& r3,
                                        uint32_t a) {
    asm volatile("ldmatrix.sync.aligned.m8n8.x4.shared.b16 {%0,%1,%2,%3}, [%4];"
                 : "=r"(r0), "=r"(r1), "=r"(r2), "=r"(r3) : "r"(a));
}
__device__ __forceinline__ void mma16816(float* c, const uint32_t* a, uint32_t b0, uint32_t b1) {
    asm volatile("mma.sync.aligned.m16n8k16.row.col.f32.bf16.bf16.f32 "
                 "{%0,%1,%2,%3}, {%4,%5,%6,%7}, {%8,%9}, {%0,%1,%2,%3};"
                 : "+f"(c[0]), "+f"(c[1]), "+f"(c[2]), "+f"(c[3])
                 : "r"(a[0]), "r"(a[1]), "r"(a[2]), "r"(a[3]), "r"(b0), "r"(b1));
}
__device__ __forceinline__ uint32_t sw128(uint32_t b) { return b ^ ((b >> 3) & 0x70); }

__device__ __forceinline__ uint16_t bfbits(float x) {
    __nv_bfloat16 h = __float2bfloat16(x);
    return *reinterpret_cast<uint16_t*>(&h);
}
__device__ __forceinline__ float bf2f(uint16_t u) {
    __nv_bfloat16 h;
    *reinterpret_cast<uint16_t*>(&h) = u;
    return __bfloat162float(h);
}

// ---------------- kernel 1: per-class column sums + counts ----------------
__global__ void k_stats(const float4* __restrict__ X4, const int* __restrict__ y) {
    const int c = blockIdx.x, cg = blockIdx.y;
    const int tid = threadIdx.x, w = tid >> 5, lane = tid & 31;
    const int4* y4 = (const int4*)y;
    float4 acc = make_float4(0.f, 0.f, 0.f, 0.f);
    int cnt = 0;
    int idx = w * 4096 + lane;
    int4 cur = y4[idx];
    for (int s = 0; s < 128; ++s) {
        int4 nxt = make_int4(0, 0, 0, 0);
        if (s < 127) nxt = y4[idx + 32];
        const int rowbase = w * 16384 + s * 128;
#pragma unroll
        for (int q = 0; q < 4; ++q) {
            int yq = (q == 0) ? cur.x : (q == 1) ? cur.y : (q == 2) ? cur.z : cur.w;
            unsigned m = __ballot_sync(0xffffffffu, yq == c);
            cnt += __popc(m);
            while (m) {
                int b = __ffs(m) - 1; m &= m - 1;
                float4 v = X4[(size_t)(rowbase + b * 4 + q) * 128 + cg * 32 + lane];
                acc.x += v.x; acc.y += v.y; acc.z += v.z; acc.w += v.w;
            }
        }
        cur = nxt; idx += 32;
    }
    __shared__ float4 sa[8][32];
    __shared__ int sc[8];
    sa[w][lane] = acc;
    if (lane == 0) sc[w] = cnt;
    __syncthreads();
    if (tid < 32) {
        float4 t = sa[0][tid];
#pragma unroll
        for (int ww = 1; ww < 8; ++ww) {
            float4 v = sa[ww][tid];
            t.x += v.x; t.y += v.y; t.z += v.z; t.w += v.w;
        }
        float* dst = &g_cls_sums[c * DDIM + cg * 128 + tid * 4];
        dst[0] = t.x; dst[1] = t.y; dst[2] = t.z; dst[3] = t.w;
    }
    if (tid == 0 && cg == 0) {
        int tot = 0;
#pragma unroll
        for (int ww = 0; ww < 8; ++ww) tot += sc[ww];
        g_counts[c] = (float)tot;
    }
}

// ---------------- kernel 2: means / weights ----------------
__global__ void k_small(float* __restrict__ o_mu) {
    const int t = threadIdx.x;
    if (t < DDIM) {
        float s = 0.f;
        for (int c = 0; c < NCLS; ++c) s += g_cls_sums[c * DDIM + t];
        float mean = s / (float)NROWS;
        g_mean[t] = mean;
        o_mu[t] = mean;
    }
    if (t < NCLS) {
        float cnt = g_counts[t];
        float wc = cnt / fmaxf(cnt - 1.0f, 1.0f) / (float)NROWS;
        g_wc[t] = wc;
        g_wcc[t] = wc * cnt;
        g_cw[t] = cnt / (float)NROWS;
    }
    for (int i = t; i < NCLS * DDIM; i += 512) {
        int c = i >> 9;
        g_cmean[i] = g_cls_sums[i] / fmaxf(g_counts[c], 1.0f);
    }
}

// ---------------- kernel 2b: per-row weight ----------------
__global__ void k_wrow(const int* __restrict__ y) {
    int n = blockIdx.x * 512 + threadIdx.x;
    g_wrow[n] = g_wc[y[n]];
}

// ---------------- kernel 3: transpose + bf16 split (vectorized uint4 stores) ----------------
__global__ void k_convert(const float* __restrict__ X) {
    __shared__ float t[64][65];
    __shared__ float wv[64];
    const int n0 = blockIdx.x * 64, d0 = blockIdx.y * 64;
    const int tid = threadIdx.x;
#pragma unroll
    for (int q = 0; q < 4; ++q) {
        int f = tid + q * 256;            // float4 units, 0..1023
        int r = f >> 4, c = (f & 15) * 4;
        float4 v = *(const float4*)&X[(size_t)(n0 + r) * DDIM + d0 + c];
        t[r][c] = v.x; t[r][c + 1] = v.y; t[r][c + 2] = v.z; t[r][c + 3] = v.w;
    }
    if (tid < 64) wv[tid] = g_wrow[n0 + tid];
    __syncthreads();
#pragma unroll
    for (int q = 0; q < 2; ++q) {
        int s = tid + q * 256;            // 0..511
        int d = s >> 3, nb = (s & 7) * 8;
        uint32_t Hh[4], Ll[4], Ww[4];
#pragma unroll
        for (int p = 0; p < 4; ++p) {
            float x0 = t[nb + 2 * p][d],     x1 = t[nb + 2 * p + 1][d];
            float w0 = wv[nb + 2 * p],       w1 = wv[nb + 2 * p + 1];
            uint16_t h0 = bfbits(x0),        h1 = bfbits(x1);
            uint16_t l0 = bfbits(x0 - bf2f(h0)), l1 = bfbits(x1 - bf2f(h1));
            uint16_t q0 = bfbits(w0 * x0),   q1 = bfbits(w1 * x1);
            Hh[p] = (uint32_t)h0 | ((uint32_t)h1 << 16);
            Ll[p] = (uint32_t)l0 | ((uint32_t)l1 << 16);
            Ww[p] = (uint32_t)q0 | ((uint32_t)q1 << 16);
        }
        size_t o = ((size_t)(d0 + d) * NROWS + n0 + nb) >> 3;  // uint4 index
        ((uint4*)g_H)[o]  = make_uint4(Hh[0], Hh[1], Hh[2], Hh[3]);
        ((uint4*)g_L)[o]  = make_uint4(Ll[0], Ll[1], Ll[2], Ll[3]);
        ((uint4*)g_WH)[o] = make_uint4(Ww[0], Ww[1], Ww[2], Ww[3]);
    }
}

// ---------------- kernel 4: HMMA dual gram, 5 tiles/stage ----------------
// Warps 0-3: G1 = Hi*Hj + Hi*Lj + Li*Hj. Warps 4-7: G2 = Hi*WHj + Li*WHj.
// Stage tiles: 0 Hi, 1 Li, 2 Hj, 3 Lj, 4 WHj; each [128 rows x 64 bf16] SW128 = 16KB.
#define STAGE_BYTES (5 * 16384)

__global__ __launch_bounds__(256, 1)
void k_gram_mma() {
    extern __shared__ char dsm[];
    const uint32_t sbase = (smem_u32(dsm) + 1023u) & ~1023u;

    const int tile = blockIdx.x % NTILES;
    const int sp   = blockIdx.x / NTILES;
    const int bi = c_bi[tile] * 128, bj = c_bj[tile] * 128;
    const int kb0 = (NKB * sp) / SPLITS;
    const int kb1 = (NKB * (sp + 1)) / SPLITS;
    const int n = kb1 - kb0;

    const int tid = threadIdx.x;
    const int w = tid >> 5, lane = tid & 31;
    const int grp = w >> 2;              // 0 = G1, 1 = G2
    const int wm = w & 1, wn = (w >> 1) & 1;

    auto load_stage = [&](int stg, int kb) {
        uint32_t stb = sbase + stg * STAGE_BYTES;
#pragma unroll
        for (int i = 0; i < 20; ++i) {
            const int t5 = i >> 2;
            int rem = (i & 3) * 256 + tid;
            int r = rem >> 3, c = rem & 7;
            uint32_t sw = sw128((uint32_t)(r * 128 + c * 16));
            const __nv_bfloat16* base;
            int row;
            if      (t5 == 0) { base = g_H;  row = bi; }
            else if (t5 == 1) { base = g_L;  row = bi; }
            else if (t5 == 2) { base = g_H;  row = bj; }
            else if (t5 == 3) { base = g_L;  row = bj; }
            else              { base = g_WH; row = bj; }
            const void* g = base + (size_t)(row + r) * NROWS + (size_t)kb * KBLK + c * 8;
            cp_async16(stb + t5 * 16384 + sw, g);
        }
        CP_COMMIT();
    };

    float acc[4][8][4];
#pragma unroll
    for (int m = 0; m < 4; ++m)
#pragma unroll
        for (int nn = 0; nn < 8; ++nn)
#pragma unroll
            for (int q = 0; q < 4; ++q) acc[m][nn][q] = 0.f;

    const uint32_t a_off = (uint32_t)((wm * 64 + (lane & 15)) * 128 + (lane >> 4) * 16);
    const uint32_t b_off = (uint32_t)((wn * 64 + (lane & 15)) * 128 + (lane >> 4) * 16);

    const uint32_t tHi = 0, tLi = 16384;
    const uint32_t tHj = 2 * 16384, tLj = 3 * 16384, tWj = 4 * 16384;

    load_stage(0, kb0);

    for (int i = 0; i < n; ++i) {
        const int b = i & 1;
        if (i + 1 < n) { load_stage(b ^ 1, kb0 + i + 1); CP_WAIT1(); }
        else           { CP_WAIT0(); }
        __syncthreads();

        const uint32_t st = sbase + b * STAGE_BYTES;
#pragma unroll
        for (int ks = 0; ks < 4; ++ks) {
            const uint32_t kb_byte = ks * 32;
            uint32_t aH[4][4], aL[4][4];
#pragma unroll
            for (int m = 0; m < 4; ++m) {
                uint32_t off = a_off + (uint32_t)(m * 16 * 128) + kb_byte;
                ldsm_x4(aH[m][0], aH[m][1], aH[m][2], aH[m][3], st + tHi + sw128(off));
                ldsm_x4(aL[m][0], aL[m][1], aL[m][2], aL[m][3], st + tLi + sw128(off));
            }
#pragma unroll
            for (int nt2 = 0; nt2 < 4; ++nt2) {
                uint32_t off = b_off + (uint32_t)(nt2 * 16 * 128) + kb_byte;
                if (grp == 0) {
                    uint32_t bh0, bh1, bh2, bh3, bl0, bl1, bl2, bl3;
                    ldsm_x4(bh0, bh1, bh2, bh3, st + tHj + sw128(off));
                    ldsm_x4(bl0, bl1, bl2, bl3, st + tLj + sw128(off));
#pragma unroll
                    for (int m = 0; m < 4; ++m) {
                        float* c0 = acc[m][nt2 * 2];
                        float* c1 = acc[m][nt2 * 2 + 1];
                        mma16816(c0, aH[m], bh0, bh2);
                        mma16816(c0, aH[m], bl0, bl2);
                        mma16816(c0, aL[m], bh0, bh2);
                        mma16816(c1, aH[m], bh1, bh3);
                        mma16816(c1, aH[m], bl1, bl3);
                        mma16816(c1, aL[m], bh1, bh3);
                    }
                } else {
                    uint32_t bw0, bw1, bw2, bw3;
                    ldsm_x4(bw0, bw1, bw2, bw3, st + tWj + sw128(off));
#pragma unroll
                    for (int m = 0; m < 4; ++m) {
                        float* c0 = acc[m][nt2 * 2];
                        float* c1 = acc[m][nt2 * 2 + 1];
                        mma16816(c0, aH[m], bw0, bw2);
                        mma16816(c0, aL[m], bw0, bw2);
                        mma16816(c1, aH[m], bw1, bw3);
                        mma16816(c1, aL[m], bw1, bw3);
                    }
                }
            }
        }
        __syncthreads();
    }

    float* P = (grp == 0 ? g_P1 : g_P2) + (size_t)sp * MAT;
#pragma unroll
    for (int m = 0; m < 4; ++m) {
#pragma unroll
        for (int nn = 0; nn < 8; ++nn) {
            int row = bi + wm * 64 + m * 16 + (lane >> 2);
            int col = bj + wn * 64 + nn * 8 + (lane & 3) * 2;
            *(float2*)&P[(size_t)row * DDIM + col]       = make_float2(acc[m][nn][0], acc[m][nn][1]);
            *(float2*)&P[(size_t)(row + 8) * DDIM + col] = make_float2(acc[m][nn][2], acc[m][nn][3]);
        }
    }
}

// ---------------- kernel 5: finalize (sums split-K partials inline) ----------------
__global__ void k_finalize(float* __restrict__ out) {
    float* o_sw = out + DDIM + MAT;
    float* o_sb = out + DDIM + 2 * MAT;
    float* o_st = out + DDIM + 3 * MAT;

    __shared__ float cmi[NCLS][16], cmj[NCLS][16];
    __shared__ float swcc[NCLS], scw[NCLS];

    const int tx = threadIdx.x, ty = threadIdx.y;
    const int tid = ty * 16 + tx;
    const int i0 = blockIdx.y * 16, j0 = blockIdx.x * 16;

    for (int idx = tid; idx < NCLS * 16; idx += 256) {
        int c = idx / 16, r = idx % 16;
        cmi[c][r] = g_cmean[c * DDIM + i0 + r];
        cmj[c][r] = g_cmean[c * DDIM + j0 + r];
    }
    if (tid < NCLS) { swcc[tid] = g_wcc[tid]; scw[tid] = g_cw[tid]; }
    __syncthreads();

    const int i = i0 + ty, j = j0 + tx;
    const float mi = g_mean[i], mj = g_mean[j];
    float swc = 0.f, sbv = 0.f;
#pragma unroll 4
    for (int c = 0; c < NCLS; ++c) {
        float a = cmi[c][ty], b = cmj[c][tx];
        swc += swcc[c] * a * b;
        sbv += scw[c] * (a - mi) * (b - mj);
    }

    int gidx = ((i >> 7) >= (j >> 7)) ? (i * DDIM + j) : (j * DDIM + i);
    float g1 = 0.f, g2 = 0.f;
#pragma unroll
    for (int s = 0; s < SPLITS; ++s) {
        g1 += g_P1[(size_t)s * MAT + gidx];
        g2 += g_P2[(size_t)s * MAT + gidx];
    }

    float st = (g1 - (float)NROWS * mi * mj) * (1.0f / ((float)NROWS - 1.0f));
    float sw = g2 - swc;

    o_sw[i * DDIM + j] = sw;
    o_sb[i * DDIM + j] = sbv;
    o_st[i * DDIM + j] = st;
    g_M[i * DDIM + j] = sw + ((i == j) ? LAMBDA : 0.0f);
}

// ---------------- kernel 6: Gershgorin bound (column abs sums; M symmetric) ----------------
__global__ void k_rowmax() {
    const int t = threadIdx.x;
    float s = 0.f;
    for (int i = 0; i < DDIM; ++i) s += fabsf(g_M[i * DDIM + t]);
    __shared__ float sh[512];
    sh[t] = s;
    __syncthreads();
    for (int o = 256; o > 0; o >>= 1) {
        if (t < o) sh[t] = fmaxf(sh[t], sh[t + o]);
        __syncthreads();
    }
    if (t == 0) g_invR = 1.0f / sh[0];
}

// ---------------- kernel 7: analytic first NS step: X1 = (2/R) I - M / R^2 ----------------
__global__ void k_ns_init() {
    int idx = blockIdx.x * 512 + threadIdx.x;
    float r = g_invR;
    float v = -g_M[idx] * r * r;
    if ((idx >> 9) == (idx & 511)) v += 2.0f * r;
    g_XA[idx] = v;
}

__device__ __forceinline__ float* selptr(int s, float* out) {
    switch (s) {
        case 0: return g_M;
        case 1: return g_XA;
        case 2: return g_XB;
        case 3: return g_T;
        default: return out + DDIM + 2 * MAT;  // Sb
    }
}

// ---------------- kernel 8: 512^3 GEMM, 32x64 tile, 2x4 micro; mode 1: C = 2A - A@B ----------------
__global__ __launch_bounds__(256)
void k_gemm512(int aSel, int bSel, int cSel, int mode, float* __restrict__ out) {
    const float* A = selptr(aSel, out);
    const float* B = selptr(bSel, out);
    float* C = selptr(cSel, out);

    __shared__ float As[32][33];
    __shared__ float Bs[32][68];

    const int tx = threadIdx.x, ty = threadIdx.y;
    const int tid = ty * 16 + tx;
    const int i0 = blockIdx.y * 32, j0 = blockIdx.x * 64;

    float acc[2][4];
#pragma unroll
    for (int r = 0; r < 2; ++r)
#pragma unroll
        for (int c = 0; c < 4; ++c) acc[r][c] = 0.f;

    for (int k0 = 0; k0 < DDIM; k0 += 32) {
        __syncthreads();
#pragma unroll
        for (int q = 0; q < 4; ++q) {
            int idx = tid + q * 256;
            As[idx >> 5][idx & 31] = A[(size_t)(i0 + (idx >> 5)) * DDIM + k0 + (idx & 31)];
        }
#pragma unroll
        for (int q = 0; q < 8; ++q) {
            int idx = tid + q * 256;
            Bs[idx >> 6][idx & 63] = B[(size_t)(k0 + (idx >> 6)) * DDIM + j0 + (idx & 63)];
        }
        __syncthreads();
#pragma unroll
        for (int k = 0; k < 32; ++k) {
            float a0 = As[ty * 2][k], a1 = As[ty * 2 + 1][k];
            float4 b4 = *(const float4*)&Bs[k][tx * 4];
            acc[0][0] += a0 * b4.x; acc[0][1] += a0 * b4.y;
            acc[0][2] += a0 * b4.z; acc[0][3] += a0 * b4.w;
            acc[1][0] += a1 * b4.x; acc[1][1] += a1 * b4.y;
            acc[1][2] += a1 * b4.z; acc[1][3] += a1 * b4.w;
        }
    }

    const int i = i0 + ty * 2, j = j0 + tx * 4;
#pragma unroll
    for (int r = 0; r < 2; ++r) {
        if (mode == 1) {
#pragma unroll
            for (int c = 0; c < 4; ++c)
                C[(size_t)(i + r) * DDIM + j + c] =
                    2.0f * A[(size_t)(i + r) * DDIM + j + c] - acc[r][c];
        } else {
#pragma unroll
            for (int c = 0; c < 4; ++c)
                C[(size_t)(i + r) * DDIM + j + c] = acc[r][c];
        }
    }
}

// ---------------- kernel 9: temp = (T + T^T)/2 ----------------
__global__ void k_symmetrize(float* __restrict__ out) {
    int idx = blockIdx.x * 512 + threadIdx.x;
    int i = idx >> 9, j = idx & 511;
    out[DDIM + idx] = 0.5f * (g_T[i * DDIM + j] + g_T[j * DDIM + i]);
}

// ---------------- launcher ----------------
extern "C" void kernel_launch(void* const* d_in, const int* in_sizes, int n_in,
                              void* d_out, int out_size) {
    const float* X = (const float*)d_in[0];
    const int* y = (const int*)d_in[1];
    float* out = (float*)d_out;

    const int gram_smem = 2 * STAGE_BYTES + 1024;
    cudaFuncSetAttribute(k_gram_mma, cudaFuncAttributeMaxDynamicSharedMemorySize, gram_smem);

    k_stats<<<dim3(NCLS, 4), 256>>>((const float4*)X, y);
    k_small<<<1, 512>>>(out);
    k_wrow<<<NROWS / 512, 512>>>(y);
    k_convert<<<dim3(NROWS / 64, DDIM / 64), 256>>>(X);
    k_gram_mma<<<NTILES * SPLITS, 256, gram_smem>>>();
    k_finalize<<<dim3(32, 32), dim3(16, 16)>>>(out);
    k_rowmax<<<1, 512>>>();
    k_ns_init<<<MAT / 512, 512>>>();

    dim3 gg(8, 16), gb(16, 16);
    int cur = 1, nxt = 2;
    for (int it = 0; it < 5; ++it) {
        k_gemm512<<<gg, gb>>>(0, cur, 3, 0, out);   // T = M @ X
        k_gemm512<<<gg, gb>>>(cur, 3, nxt, 1, out); // Xn = 2X - X@T
        int tmp = cur; cur = nxt; nxt = tmp;
    }
    k_gemm512<<<gg, gb>>>(cur, 4, 3, 0, out);       // T = inv(M) @ Sb
    k_symmetrize<<<MAT / 512, 512>>>(out);
}